// round 1
// baseline (speedup 1.0000x reference)
#include <cuda_runtime.h>

#define B_      2
#define N_      20000
#define C_      20
#define MAXD    300
#define LANES   (B_ * C_)
#define NBUCK   4096
#define TILE_C  4096
#define NEG_    (-1000000000.0f)
#define THREADS 1024
#define ITEMS   ((N_ + THREADS - 1) / THREADS)

// ---------------- scratch (device globals; no allocation) ----------------
__device__ unsigned long long g_keys[LANES * N_];          // bucketed keys per lane
__device__ int                g_bstart[LANES * (NBUCK+1)]; // consumed-order bucket offsets
__device__ int                g_total[LANES];
__device__ int                g_sel_idx[LANES * MAXD];
__device__ float              g_sel_score[LANES * MAXD];
__device__ int                g_nacc[LANES];

// key = sortable(score) << 32 | ~idx  (score > 0 here, so sortable = bits | signbit)
// larger key == higher score, ties -> smaller idx (matches jnp.argmax first-index).

// ============================ Kernel 1: bucketize ============================
__global__ __launch_bounds__(THREADS) void bucket_kernel(const float* __restrict__ cls) {
    __shared__ int counts[NBUCK];
    __shared__ int wsum[32];

    const int L = blockIdx.x, b = L / C_, c = L % C_;
    const int tid = threadIdx.x;

    for (int i = tid; i < NBUCK; i += THREADS) counts[i] = 0;
    __syncthreads();

    // pass 1: histogram of above-threshold scores
    for (int k = 0; k < ITEMS; k++) {
        int i = tid + k * THREADS;
        if (i < N_) {
            float s = cls[((size_t)b * N_ + i) * C_ + c];
            if (s > 0.05f) {
                int bk = (int)(s * (float)NBUCK);
                if (bk > NBUCK - 1) bk = NBUCK - 1;
                atomicAdd(&counts[bk], 1);
            }
        }
    }
    __syncthreads();

    // exclusive scan in consumed order j (bucket NBUCK-1-j), 4 buckets/thread
    const int j0 = tid * 4;
    int v0 = counts[NBUCK - 1 - (j0 + 0)];
    int v1 = counts[NBUCK - 1 - (j0 + 1)];
    int v2 = counts[NBUCK - 1 - (j0 + 2)];
    int v3 = counts[NBUCK - 1 - (j0 + 3)];
    int p0 = v0, p1 = p0 + v1, p2 = p1 + v2, p3 = p2 + v3;

    const int lane = tid & 31, wid = tid >> 5;
    int incl = p3;
    #pragma unroll
    for (int o = 1; o < 32; o <<= 1) {
        int t = __shfl_up_sync(0xffffffffu, incl, o);
        if (lane >= o) incl += t;
    }
    if (lane == 31) wsum[wid] = incl;
    __syncthreads();
    if (wid == 0) {
        int x = wsum[lane];
        #pragma unroll
        for (int o = 1; o < 32; o <<= 1) {
            int t = __shfl_up_sync(0xffffffffu, x, o);
            if (lane >= o) x += t;
        }
        wsum[lane] = x; // inclusive warp sums
    }
    __syncthreads();

    int warpbase = (wid == 0) ? 0 : wsum[wid - 1];
    int texcl = warpbase + (incl - p3);
    int st0 = texcl, st1 = texcl + p0, st2 = texcl + p1, st3 = texcl + p2;

    int* bstart = g_bstart + (size_t)L * (NBUCK + 1);
    bstart[j0 + 0] = st0; bstart[j0 + 1] = st1;
    bstart[j0 + 2] = st2; bstart[j0 + 3] = st3;
    __syncthreads();

    // turn counts into scatter cursors (start offsets, indexed by bucket id)
    counts[NBUCK - 1 - (j0 + 0)] = st0;
    counts[NBUCK - 1 - (j0 + 1)] = st1;
    counts[NBUCK - 1 - (j0 + 2)] = st2;
    counts[NBUCK - 1 - (j0 + 3)] = st3;
    if (tid == 0) {
        int total = wsum[31];
        bstart[NBUCK] = total;
        g_total[L] = total;
    }
    __syncthreads();

    // pass 2: scatter keys (within-bucket order arbitrary; fixed by tile sort later)
    unsigned long long* keys = g_keys + (size_t)L * N_;
    for (int k = 0; k < ITEMS; k++) {
        int i = tid + k * THREADS;
        if (i < N_) {
            float s = cls[((size_t)b * N_ + i) * C_ + c];
            if (s > 0.05f) {
                int bk = (int)(s * (float)NBUCK);
                if (bk > NBUCK - 1) bk = NBUCK - 1;
                int pos = atomicAdd(&counts[bk], 1);
                unsigned sb = __float_as_uint(s) | 0x80000000u; // s>0
                keys[pos] = ((unsigned long long)sb << 32) | (unsigned)(~(unsigned)i);
            }
        }
    }
}

// ============================ Kernel 2: greedy NMS ============================
__global__ __launch_bounds__(THREADS) void nms_kernel(const float4* __restrict__ boxes) {
    __shared__ unsigned long long tile[TILE_C];
    __shared__ float4 acc_box[MAXD];
    __shared__ float  acc_area[MAXD];
    __shared__ float4 ch_box[32];
    __shared__ float  ch_area[32];
    __shared__ unsigned char ext_ok[32];
    __shared__ unsigned int  intra_mask[32];
    __shared__ unsigned int  accept_mask;
    __shared__ int sh_e;

    const int L = blockIdx.x, b = L / C_;
    const int tid = threadIdx.x, w = tid >> 5, ln = tid & 31;
    const unsigned long long* keys = g_keys + (size_t)L * N_;
    const int* bstart = g_bstart + (size_t)L * (NBUCK + 1);
    const int total = g_total[L];

    int nacc = 0, cur = 0;

    while (nacc < MAXD && cur < total) {
        if (tid == 0) {
            // largest bucket boundary <= cur + TILE_C
            int limit = cur + TILE_C;
            int lo = 0, hi = NBUCK;
            while (lo < hi) {
                int mid = (lo + hi + 1) >> 1;
                if (bstart[mid] <= limit) lo = mid; else hi = mid - 1;
            }
            int e = bstart[lo];
            if (e <= cur) e = (limit < total) ? limit : total; // giant-bucket fallback
            sh_e = e;
        }
        __syncthreads();
        const int e = sh_e, cnt = e - cur;

        for (int i = tid; i < TILE_C; i += THREADS)
            tile[i] = (i < cnt) ? keys[cur + i] : 0ULL;
        __syncthreads();

        // bitonic sort descending (whole buckets => globally correct order)
        for (int k = 2; k <= TILE_C; k <<= 1)
            for (int j = k >> 1; j > 0; j >>= 1) {
                for (int i = tid; i < TILE_C; i += THREADS) {
                    int l2 = i ^ j;
                    if (l2 > i) {
                        unsigned long long a = tile[i], bb = tile[l2];
                        if ((a < bb) == ((i & k) == 0)) { tile[i] = bb; tile[l2] = a; }
                    }
                }
                __syncthreads();
            }

        const int nch = (cnt + 31) >> 5;
        for (int ch = 0; ch < nch && nacc < MAXD; ch++) {
            // one warp == one candidate
            unsigned long long key = tile[(ch << 5) + w];
            bool real = (key != 0ULL);
            int bidx = 0; float score = NEG_, area = 0.f;
            float4 bx = make_float4(0.f, 0.f, 0.f, 0.f);
            if (real) {
                bidx  = (int)~(unsigned)key;
                score = __uint_as_float((unsigned)(key >> 32) ^ 0x80000000u);
                bx    = boxes[(size_t)b * N_ + bidx];
                area  = (bx.z - bx.x) * (bx.w - bx.y);
            }
            if (ln == 0) { ch_box[w] = bx; ch_area[w] = area; }

            // external test vs accepted list (parallel over lanes, early exit)
            bool supp = !real;
            for (int r0 = 0; r0 < nacc && !supp; r0 += 32) {
                int ai = r0 + ln;
                bool s = false;
                if (ai < nacc) {
                    float4 a = acc_box[ai]; float aa = acc_area[ai];
                    float ix1 = fmaxf(a.x, bx.x), iy1 = fmaxf(a.y, bx.y);
                    float ix2 = fminf(a.z, bx.z), iy2 = fminf(a.w, bx.w);
                    float inter = fmaxf(ix2 - ix1, 0.f) * fmaxf(iy2 - iy1, 0.f);
                    float iou = __fdiv_rn(inter, aa + area - inter + 1e-8f);
                    s = iou > 0.5f;
                }
                if (__ballot_sync(0xffffffffu, s)) supp = true;
            }
            if (ln == 0) ext_ok[w] = (unsigned char)((!supp) && real);
            __syncthreads();

            // intra-chunk pairwise: lane ln tests candidate w vs candidate ln (ln < w)
            bool s2 = false;
            if (ln < w) {
                float4 o = ch_box[ln]; float oa = ch_area[ln];
                float ix1 = fmaxf(o.x, bx.x), iy1 = fmaxf(o.y, bx.y);
                float ix2 = fminf(o.z, bx.z), iy2 = fminf(o.w, bx.w);
                float inter = fmaxf(ix2 - ix1, 0.f) * fmaxf(iy2 - iy1, 0.f);
                float iou = __fdiv_rn(inter, oa + area - inter + 1e-8f);
                s2 = iou > 0.5f;
            }
            unsigned m = __ballot_sync(0xffffffffu, s2);
            if (ln == 0) intra_mask[w] = m;
            __syncthreads();

            if (tid == 0) {
                unsigned accb = 0; int n2 = nacc;
                #pragma unroll 1
                for (int t = 0; t < 32; t++) {
                    if (n2 < MAXD && ext_ok[t] && ((intra_mask[t] & accb) == 0u)) {
                        accb |= 1u << t; n2++;
                    }
                }
                accept_mask = accb;
            }
            __syncthreads();

            unsigned am = accept_mask;
            if (ln == 0 && ((am >> w) & 1u)) {
                int pos = nacc + __popc(am & ((1u << w) - 1u));
                acc_box[pos]  = bx;
                acc_area[pos] = area;
                g_sel_idx[L * MAXD + pos]   = bidx;
                g_sel_score[L * MAXD + pos] = score;
            }
            nacc += __popc(am);
            __syncthreads();
        }
        cur = e;
    }

    for (int p = nacc + tid; p < MAXD; p += THREADS) {
        g_sel_idx[L * MAXD + p]   = 0;
        g_sel_score[L * MAXD + p] = NEG_;
    }
    if (tid == 0) g_nacc[L] = nacc;
}

// ============================ Kernel 3: stable top-300 ============================
__global__ __launch_bounds__(THREADS) void topk_kernel(const float4* __restrict__ boxes,
                                                       float* __restrict__ out) {
    extern __shared__ unsigned long long sk[];  // 8192 keys
    const int b = blockIdx.x, tid = threadIdx.x;
    const int TOT = C_ * MAXD;  // 6000

    for (int i = tid; i < 8192; i += THREADS) {
        unsigned long long key = 0ULL;
        if (i < TOT) {
            int c = i / MAXD, m = i % MAXD;
            int lane = b * C_ + c;
            float s = (m < g_nacc[lane]) ? g_sel_score[lane * MAXD + m] : NEG_;
            unsigned fb = __float_as_uint(s);
            unsigned u = (fb & 0x80000000u) ? ~fb : (fb | 0x80000000u);
            key = ((unsigned long long)u << 32) | (unsigned)(~(unsigned)i);
        }
        sk[i] = key;
    }
    __syncthreads();

    for (int k = 2; k <= 8192; k <<= 1)
        for (int j = k >> 1; j > 0; j >>= 1) {
            for (int i = tid; i < 8192; i += THREADS) {
                int l2 = i ^ j;
                if (l2 > i) {
                    unsigned long long a = sk[i], bb = sk[l2];
                    if ((a < bb) == ((i & k) == 0)) { sk[i] = bb; sk[l2] = a; }
                }
            }
            __syncthreads();
        }

    if (tid < MAXD) {
        unsigned long long key = sk[tid];
        unsigned f = ~(unsigned)key;
        int c = f / MAXD, m2 = f % MAXD;
        int lane = b * C_ + c;
        bool valid = m2 < g_nacc[lane];
        float bx = -1.f, by = -1.f, bz = -1.f, bw = -1.f, sc = -1.f, lb = -1.f;
        if (valid) {
            int idx = g_sel_idx[lane * MAXD + m2];
            float4 bb = boxes[(size_t)b * N_ + idx];
            bx = bb.x; by = bb.y; bz = bb.z; bw = bb.w;
            sc = g_sel_score[lane * MAXD + m2];
            lb = (float)c;
        }
        int o = b * MAXD + tid;
        out[o * 4 + 0] = bx; out[o * 4 + 1] = by;
        out[o * 4 + 2] = bz; out[o * 4 + 3] = bw;
        out[B_ * MAXD * 4 + o] = sc;                    // scores
        out[B_ * MAXD * 4 + B_ * MAXD + o] = lb;        // labels (as float)
    }
}

// ============================ launch ============================
extern "C" void kernel_launch(void* const* d_in, const int* in_sizes, int n_in,
                              void* d_out, int out_size) {
    const float*  boxes = (const float*)d_in[0];        // (B, N, 4) f32
    const float*  cls   = (const float*)d_in[1];        // (B, N, C) f32
    float*        out   = (float*)d_out;                // [boxes|scores|labels] f32

    bucket_kernel<<<LANES, THREADS>>>(cls);
    nms_kernel<<<LANES, THREADS>>>((const float4*)boxes);

    cudaFuncSetAttribute(topk_kernel, cudaFuncAttributeMaxDynamicSharedMemorySize,
                         8192 * sizeof(unsigned long long));
    topk_kernel<<<B_, THREADS, 8192 * sizeof(unsigned long long)>>>((const float4*)boxes, out);
}

// round 2
// speedup vs baseline: 1.9075x; 1.9075x over previous
#include <cuda_runtime.h>

#define B_      2
#define N_      20000
#define C_      20
#define MAXD    300
#define LANES   (B_ * C_)
#define NBUCK   512
#define SEG     50                  // segments per image (hist/scatter blocks)
#define SEGROWS (N_ / SEG)          // 400
#define SEGELEM (SEGROWS * C_)      // 8000
#define WIN     1024
#define NEG_    (-1000000000.0f)
#define FULLM   0xffffffffu

// ---------------- scratch (device globals; no allocation) ----------------
__device__ int                g_hist_part[B_ * SEG][C_ * NBUCK]; // per-(img,seg) hist
__device__ int                g_bstart[LANES][NBUCK + 1];        // consumed-order offsets
__device__ int                g_cursor[LANES][NBUCK];            // scatter cursors
__device__ int                g_total[LANES];
__device__ unsigned long long g_keys[LANES][N_];
__device__ int                g_sel_idx[LANES][MAXD];
__device__ float              g_sel_score[LANES][MAXD];
__device__ int                g_nacc[LANES];

// key = sortable(score)<<32 | ~idx ; score>0 so sortable = bits|signbit.
// larger key == higher score; ties -> smaller idx (jnp.argmax first-index).

__device__ __forceinline__ bool iou_gt(float4 a, float aa, float4 c, float ca) {
    float ix1 = fmaxf(a.x, c.x), iy1 = fmaxf(a.y, c.y);
    float ix2 = fminf(a.z, c.z), iy2 = fminf(a.w, c.w);
    float inter = fmaxf(ix2 - ix1, 0.f) * fmaxf(iy2 - iy1, 0.f);
    float iou = __fdiv_rn(inter, aa + ca - inter + 1e-8f);
    return iou > 0.5f;
}

// Descending bitonic sort of 1024 u64 keys, one per thread. sbuf: u64[1024].
__device__ __forceinline__ unsigned long long
block_sort_desc_1024(unsigned long long key, unsigned long long* sbuf, int tid) {
    for (int k = 2; k <= 1024; k <<= 1) {
        int j = k >> 1;
        for (; j >= 32; j >>= 1) {
            sbuf[tid] = key;
            __syncthreads();
            unsigned long long other = sbuf[tid ^ j];
            bool dirDesc = ((tid & k) == 0);
            bool keepMax = (((tid & j) == 0) == dirDesc);
            key = keepMax ? (key > other ? key : other)
                          : (key > other ? other : key);
            __syncthreads();
        }
        for (; j >= 1; j >>= 1) {
            unsigned long long other = __shfl_xor_sync(FULLM, key, j);
            bool dirDesc = ((tid & k) == 0);
            bool keepMax = (((tid & j) == 0) == dirDesc);
            key = keepMax ? (key > other ? key : other)
                          : (key > other ? other : key);
        }
    }
    return key;
}

// ============================ Kernel A: per-segment histogram ============================
__global__ __launch_bounds__(512) void hist_kernel(const float* __restrict__ cls) {
    __shared__ int h[C_ * NBUCK]; // 40KB
    const int blk = blockIdx.x, b = blk / SEG, s = blk % SEG;
    for (int i = threadIdx.x; i < C_ * NBUCK; i += 512) h[i] = 0;
    __syncthreads();
    const float* base = cls + (size_t)b * (N_ * C_) + (size_t)s * SEGELEM;
    for (int f = threadIdx.x; f < SEGELEM; f += 512) {
        float v = base[f];
        if (v > 0.05f) {
            int c = f % C_;
            int bk = (int)(v * (float)NBUCK);
            if (bk > NBUCK - 1) bk = NBUCK - 1;
            atomicAdd(&h[c * NBUCK + bk], 1);
        }
    }
    __syncthreads();
    int* dst = g_hist_part[blk];
    for (int i = threadIdx.x; i < C_ * NBUCK; i += 512) dst[i] = h[i];
}

// ============================ Kernel B: scan -> bstart/cursors ============================
__global__ __launch_bounds__(NBUCK) void scan_kernel() {
    __shared__ int wsum[16];
    const int L = blockIdx.x, b = L / C_, c = L % C_;
    const int j = threadIdx.x;          // consumed rank
    const int bkid = NBUCK - 1 - j;     // bucket id (descending score)
    int v = 0;
    #pragma unroll 5
    for (int s = 0; s < SEG; s++) v += g_hist_part[b * SEG + s][c * NBUCK + bkid];

    const int lane = j & 31, w = j >> 5;
    int incl = v;
    #pragma unroll
    for (int o = 1; o < 32; o <<= 1) {
        int t = __shfl_up_sync(FULLM, incl, o);
        if (lane >= o) incl += t;
    }
    if (lane == 31) wsum[w] = incl;
    __syncthreads();
    if (w == 0 && lane < 16) {
        int x = wsum[lane];
        #pragma unroll
        for (int o = 1; o < 16; o <<= 1) {
            int t = __shfl_up_sync(0xffffu, x, o);
            if (lane >= o) x += t;
        }
        wsum[lane] = x;
    }
    __syncthreads();
    int excl = ((w > 0) ? wsum[w - 1] : 0) + incl - v;
    g_bstart[L][j] = excl;
    g_cursor[L][bkid] = excl;
    if (j == NBUCK - 1) {
        g_bstart[L][NBUCK] = excl + v;
        g_total[L] = excl + v;
    }
}

// ============================ Kernel C: scatter keys ============================
__global__ __launch_bounds__(512) void scatter_kernel(const float* __restrict__ cls) {
    const int blk = blockIdx.x, b = blk / SEG, s = blk % SEG;
    const float* base = cls + (size_t)b * (N_ * C_) + (size_t)s * SEGELEM;
    const int row0 = s * SEGROWS;
    for (int f = threadIdx.x; f < SEGELEM; f += 512) {
        float v = base[f];
        if (v > 0.05f) {
            int c = f % C_;
            int i = row0 + f / C_;
            int bk = (int)(v * (float)NBUCK);
            if (bk > NBUCK - 1) bk = NBUCK - 1;
            int L = b * C_ + c;
            int pos = atomicAdd(&g_cursor[L][bk], 1);
            unsigned sb = __float_as_uint(v) | 0x80000000u;
            g_keys[L][pos] = ((unsigned long long)sb << 32) | (unsigned)(~(unsigned)i);
        }
    }
}

// ============================ Kernel D: greedy NMS (window + survivors) ============================
__global__ __launch_bounds__(1024) void nms_kernel(const float4* __restrict__ boxes) {
    __shared__ unsigned long long s_key[WIN];   // sort buffer + survivor keys
    __shared__ float4 s_box[WIN];
    __shared__ float  s_area[WIN];
    __shared__ float4 acc_box[MAXD];
    __shared__ float  acc_area[MAXD];
    __shared__ int    s_wcnt[32];
    __shared__ int    s_S;
    __shared__ int    s_e;
    __shared__ unsigned char s_ext[32];
    __shared__ unsigned int  s_intra[32];
    __shared__ unsigned int  s_accept;

    const int L = blockIdx.x, b = L / C_;
    const int tid = threadIdx.x, w = tid >> 5, ln = tid & 31;
    const int total = g_total[L];

    int nacc = 0, cur = 0;

    while (nacc < MAXD && cur < total) {
        // ---- window = whole buckets, <= WIN keys ----
        if (tid == 0) {
            int limit = cur + WIN;
            int lo = 0, hi = NBUCK;
            while (lo < hi) {
                int mid = (lo + hi + 1) >> 1;
                if (g_bstart[L][mid] <= limit) lo = mid; else hi = mid - 1;
            }
            int e = g_bstart[L][lo];
            if (e <= cur) e = (limit < total) ? limit : total; // >WIN bucket fallback
            s_e = e;
        }
        __syncthreads();
        const int e = s_e, cnt = e - cur;

        unsigned long long key = (tid < cnt) ? g_keys[L][cur + tid] : 0ULL;
        key = block_sort_desc_1024(key, s_key, tid);

        // ---- per-thread data + external filter vs all accepted so far ----
        bool real = (key != 0ULL);
        float4 bx = make_float4(0.f, 0.f, 0.f, 0.f);
        float area = 0.f;
        if (real) {
            int bidx = (int)~(unsigned)key;
            bx = boxes[(size_t)b * N_ + bidx];
            area = (bx.z - bx.x) * (bx.w - bx.y);
        }
        bool alive = real;
        for (int r = 0; r < nacc && alive; r++) {
            if (iou_gt(acc_box[r], acc_area[r], bx, area)) alive = false;
        }

        // ---- compact survivors (order-preserving) ----
        unsigned ball = __ballot_sync(FULLM, alive);
        if (ln == 0) s_wcnt[w] = __popc(ball);
        __syncthreads();
        if (w == 0) {
            int x = s_wcnt[ln];
            int incl = x;
            #pragma unroll
            for (int o = 1; o < 32; o <<= 1) {
                int t = __shfl_up_sync(FULLM, incl, o);
                if (ln >= o) incl += t;
            }
            s_wcnt[ln] = incl - x;
            if (ln == 31) s_S = incl;
        }
        __syncthreads();
        const int S = s_S;
        if (alive) {
            int pos = s_wcnt[w] + __popc(ball & ((1u << ln) - 1u));
            s_key[pos]  = key;
            s_box[pos]  = bx;
            s_area[pos] = area;
        }
        __syncthreads();

        // ---- greedy over survivors, 32 per chunk (one warp per candidate) ----
        const int nacc0 = nacc;
        for (int c0 = 0; c0 < S && nacc < MAXD; c0 += 32) {
            int q = c0 + w;
            bool has = q < S;
            float4 cb = make_float4(0.f, 0.f, 0.f, 0.f);
            float ca = 0.f;
            unsigned long long ck = 0ULL;
            if (has) { cb = s_box[q]; ca = s_area[q]; ck = s_key[q]; }

            // external vs boxes accepted during THIS window only
            bool supp = !has;
            for (int r0 = nacc0; r0 < nacc && !supp; r0 += 32) {
                int ai = r0 + ln;
                bool sbit = false;
                if (ai < nacc) sbit = iou_gt(acc_box[ai], acc_area[ai], cb, ca);
                if (__ballot_sync(FULLM, sbit)) supp = true;
            }
            // intra-chunk: lane ln = earlier candidate c0+ln vs candidate q
            bool s2 = false;
            if (ln < w && (c0 + ln) < S)
                s2 = iou_gt(s_box[c0 + ln], s_area[c0 + ln], cb, ca);
            unsigned m = __ballot_sync(FULLM, s2);
            if (ln == 0) { s_ext[w] = (unsigned char)(!supp && has); s_intra[w] = m; }
            __syncthreads();

            if (tid == 0) {
                unsigned accb = 0; int n2 = nacc;
                #pragma unroll 1
                for (int t = 0; t < 32; t++) {
                    if (n2 < MAXD && s_ext[t] && ((s_intra[t] & accb) == 0u)) {
                        accb |= 1u << t; n2++;
                    }
                }
                s_accept = accb;
            }
            __syncthreads();

            unsigned am = s_accept;
            if (ln == 0 && ((am >> w) & 1u)) {
                int pos = nacc + __popc(am & ((1u << w) - 1u));
                acc_box[pos]  = cb;
                acc_area[pos] = ca;
                g_sel_idx[L][pos]   = (int)~(unsigned)ck;
                g_sel_score[L][pos] = __uint_as_float((unsigned)(ck >> 32) ^ 0x80000000u);
            }
            nacc += __popc(am);
            __syncthreads();
        }
        cur = e;
    }
    if (tid == 0) g_nacc[L] = nacc;
}

// ============================ Kernel E: top-300 via radix-select + sort ============================
__global__ __launch_bounds__(1024) void topk_kernel(const float4* __restrict__ boxes,
                                                    float* __restrict__ out) {
    __shared__ int hist[1024];
    __shared__ int wsum[32];
    __shared__ int s_bt, s_pos;
    __shared__ unsigned long long sk[1024];

    const int b = blockIdx.x, tid = threadIdx.x;
    const int lane = tid & 31, w = tid >> 5;
    const int TOT = C_ * MAXD; // 6000

    hist[tid] = 0;
    sk[tid] = 0ULL;
    if (tid == 0) s_pos = 0;
    __syncthreads();

    for (int t = tid; t < TOT; t += 1024) {
        int c = t / MAXD, m = t % MAXD;
        int Ln = b * C_ + c;
        if (m < g_nacc[Ln]) {
            float s = g_sel_score[Ln][m];
            int bk = (int)(s * 1024.f);
            if (bk > 1023) bk = 1023;
            atomicAdd(&hist[bk], 1);
        }
    }
    __syncthreads();

    // inclusive scan over consumed order j (bucket 1023-j) -> suffix counts
    int v = hist[1023 - tid];
    int incl = v;
    #pragma unroll
    for (int o = 1; o < 32; o <<= 1) {
        int t = __shfl_up_sync(FULLM, incl, o);
        if (lane >= o) incl += t;
    }
    if (lane == 31) wsum[w] = incl;
    __syncthreads();
    if (w == 0) {
        int x = wsum[lane];
        #pragma unroll
        for (int o = 1; o < 32; o <<= 1) {
            int t = __shfl_up_sync(FULLM, x, o);
            if (lane >= o) x += t;
        }
        wsum[lane] = x;
    }
    __syncthreads();
    int suffix = ((w > 0) ? wsum[w - 1] : 0) + incl;          // inclusive suffix count at rank tid
    int suffix_prev = suffix - v;
    if (suffix >= MAXD && suffix_prev < MAXD) s_bt = 1023 - tid;    // threshold bucket
    if (tid == 1023 && suffix < MAXD) s_bt = 0;                     // fewer than 300 valid: take all
    __syncthreads();
    const int bt = s_bt;

    // compact candidates with bucket >= bt
    for (int t = tid; t < TOT; t += 1024) {
        int c = t / MAXD, m = t % MAXD;
        int Ln = b * C_ + c;
        if (m < g_nacc[Ln]) {
            float s = g_sel_score[Ln][m];
            int bk = (int)(s * 1024.f);
            if (bk > 1023) bk = 1023;
            if (bk >= bt) {
                unsigned sb = __float_as_uint(s) | 0x80000000u;
                unsigned long long key = ((unsigned long long)sb << 32) | (unsigned)(~(unsigned)t);
                int pos = atomicAdd(&s_pos, 1);
                if (pos < 1024) sk[pos] = key;
            }
        }
    }
    __syncthreads();

    unsigned long long key = sk[tid];
    __syncthreads();
    key = block_sort_desc_1024(key, sk, tid);

    if (tid < MAXD) {
        float bx = -1.f, by = -1.f, bz = -1.f, bw = -1.f, sc = -1.f, lb = -1.f;
        if (key != 0ULL) {
            unsigned f = ~(unsigned)key;
            int c = f / MAXD, m = f % MAXD;
            int Ln = b * C_ + c;
            int idx = g_sel_idx[Ln][m];
            float4 bb = boxes[(size_t)b * N_ + idx];
            bx = bb.x; by = bb.y; bz = bb.z; bw = bb.w;
            sc = g_sel_score[Ln][m];
            lb = (float)c;
        }
        int o = b * MAXD + tid;
        out[o * 4 + 0] = bx; out[o * 4 + 1] = by;
        out[o * 4 + 2] = bz; out[o * 4 + 3] = bw;
        out[B_ * MAXD * 4 + o] = sc;
        out[B_ * MAXD * 4 + B_ * MAXD + o] = lb;
    }
}

// ============================ launch ============================
extern "C" void kernel_launch(void* const* d_in, const int* in_sizes, int n_in,
                              void* d_out, int out_size) {
    const float* boxes = (const float*)d_in[0]; // (B, N, 4) f32
    const float* cls   = (const float*)d_in[1]; // (B, N, C) f32
    float*       out   = (float*)d_out;         // [boxes | scores | labels] f32

    hist_kernel   <<<B_ * SEG, 512>>>(cls);
    scan_kernel   <<<LANES, NBUCK>>>();
    scatter_kernel<<<B_ * SEG, 512>>>(cls);
    nms_kernel    <<<LANES, 1024>>>((const float4*)boxes);
    topk_kernel   <<<B_, 1024>>>((const float4*)boxes, out);
}

// round 3
// speedup vs baseline: 2.7534x; 1.4434x over previous
#include <cuda_runtime.h>

#define B_      2
#define N_      20000
#define C_      20
#define MAXD    300
#define LANES   (B_ * C_)
#define NBUCK   512
#define WIN     1024
#define KPT     20                 // ceil(N_/1024)
#define NEG_    (-1000000000.0f)
#define FULLM   0xffffffffu

// ---------------- scratch (device globals; no allocation) ----------------
__device__ int   g_sel_idx[LANES][MAXD];
__device__ float g_sel_score[LANES][MAXD];
__device__ int   g_nacc[LANES];

// key = sortable(score)<<32 | ~idx ; score>0 so sortable = bits|signbit.
// larger key == higher score; ties -> smaller idx (jnp.argmax first-index).

__device__ __forceinline__ bool iou_gt(float4 a, float aa, float4 c, float ca) {
    float ix1 = fmaxf(a.x, c.x), iy1 = fmaxf(a.y, c.y);
    float ix2 = fminf(a.z, c.z), iy2 = fminf(a.w, c.w);
    float inter = fmaxf(ix2 - ix1, 0.f) * fmaxf(iy2 - iy1, 0.f);
    float iou = __fdiv_rn(inter, aa + ca - inter + 1e-8f);
    return iou > 0.5f;
}

// Descending bitonic sort of 1024 u64 keys, one per thread. sbuf: u64[1024].
__device__ __forceinline__ unsigned long long
block_sort_desc_1024(unsigned long long key, unsigned long long* sbuf, int tid) {
    for (int k = 2; k <= 1024; k <<= 1) {
        int j = k >> 1;
        for (; j >= 32; j >>= 1) {
            sbuf[tid] = key;
            __syncthreads();
            unsigned long long other = sbuf[tid ^ j];
            bool dirDesc = ((tid & k) == 0);
            bool keepMax = (((tid & j) == 0) == dirDesc);
            key = keepMax ? (key > other ? key : other)
                          : (key > other ? other : key);
            __syncthreads();
        }
        for (; j >= 1; j >>= 1) {
            unsigned long long other = __shfl_xor_sync(FULLM, key, j);
            bool dirDesc = ((tid & k) == 0);
            bool keepMax = (((tid & j) == 0) == dirDesc);
            key = keepMax ? (key > other ? key : other)
                          : (key > other ? other : key);
        }
    }
    return key;
}

// ============================ fused bucketize + greedy NMS ============================
__global__ __launch_bounds__(1024, 1) void nms_fused(const float* __restrict__ cls,
                                                     const float4* __restrict__ boxes) {
    __shared__ int s_hist[NBUCK];           // histogram, then scatter cursors
    __shared__ int s_bstart[NBUCK + 1];     // consumed-order bucket offsets
    __shared__ unsigned long long s_key[WIN];
    __shared__ float4 s_box[WIN];
    __shared__ float  s_area[WIN];
    __shared__ float4 acc_box[MAXD];
    __shared__ float  acc_area[MAXD];
    __shared__ int    s_wcnt[32];
    __shared__ int    s_S, s_e;
    __shared__ unsigned char s_ext[32];
    __shared__ unsigned int  s_intra[32];
    __shared__ unsigned int  s_accept;

    const int L = blockIdx.x, b = L / C_, c = L % C_;
    const int tid = threadIdx.x, w = tid >> 5, ln = tid & 31;

    // ---- load this lane's scores into registers ----
    float sc[KPT];
    #pragma unroll
    for (int k = 0; k < KPT; k++) {
        int i = k * 1024 + tid;
        sc[k] = (i < N_) ? cls[((size_t)b * N_ + i) * C_ + c] : 0.f;
    }

    // ---- histogram ----
    if (tid < NBUCK) s_hist[tid] = 0;
    __syncthreads();
    #pragma unroll
    for (int k = 0; k < KPT; k++) {
        float v = sc[k];
        if (v > 0.05f) {
            int bk = (int)(v * (float)NBUCK);
            if (bk > NBUCK - 1) bk = NBUCK - 1;
            atomicAdd(&s_hist[bk], 1);
        }
    }
    __syncthreads();

    // ---- scan in consumed order (tid<512) ----
    int v = 0, incl = 0;
    if (tid < NBUCK) {
        v = s_hist[NBUCK - 1 - tid];
        incl = v;
        #pragma unroll
        for (int o = 1; o < 32; o <<= 1) {
            int t = __shfl_up_sync(FULLM, incl, o);
            if (ln >= o) incl += t;
        }
        if (ln == 31) s_wcnt[w] = incl;
    }
    __syncthreads();
    if (tid < 16) {
        int x = s_wcnt[tid];
        int ix = x;
        #pragma unroll
        for (int o = 1; o < 16; o <<= 1) {
            int t = __shfl_up_sync(0xffffu, ix, o);
            if (tid >= o) ix += t;
        }
        s_wcnt[tid] = ix;
    }
    __syncthreads();
    if (tid < NBUCK) {
        int excl = ((w > 0) ? s_wcnt[w - 1] : 0) + incl - v;
        s_bstart[tid] = excl;
        s_hist[NBUCK - 1 - tid] = excl;      // cursor (global consumed position)
        if (tid == NBUCK - 1) s_bstart[NBUCK] = excl + v;
    }
    __syncthreads();

    const int total = s_bstart[NBUCK];
    int nacc = 0, cur = 0;

    while (nacc < MAXD && cur < total) {
        // ---- window end: largest boundary <= cur+WIN (parallel search) ----
        {
            int limit = cur + WIN;
            if (tid <= NBUCK) {
                int bj = s_bstart[tid];
                int nxt = (tid < NBUCK) ? s_bstart[tid + 1] : 0x7fffffff;
                if (bj <= limit && nxt > limit) s_e = bj;
            }
        }
        // zero sort buffer
        s_key[tid] = 0ULL;
        __syncthreads();
        int e = s_e;
        if (e <= cur) e = min(cur + WIN, total);   // giant-bucket fallback (unreachable)

        // ---- scatter this window's keys from registers ----
        #pragma unroll
        for (int k = 0; k < KPT; k++) {
            float vv = sc[k];
            if (vv > 0.05f) {
                int bk = (int)(vv * (float)NBUCK);
                if (bk > NBUCK - 1) bk = NBUCK - 1;
                int st = s_bstart[NBUCK - 1 - bk];
                if (st >= cur && st < e) {
                    int pos = atomicAdd(&s_hist[bk], 1) - cur;
                    if (pos < WIN) {
                        unsigned sb = __float_as_uint(vv) | 0x80000000u;
                        int i = k * 1024 + tid;
                        s_key[pos] = ((unsigned long long)sb << 32) | (unsigned)(~(unsigned)i);
                    }
                }
            }
        }
        __syncthreads();

        // ---- sort window descending ----
        unsigned long long key = s_key[tid];
        key = block_sort_desc_1024(key, s_key, tid);

        // ---- per-thread box + pre-filter vs all previously accepted ----
        bool real = (key != 0ULL);
        float4 bx = make_float4(0.f, 0.f, 0.f, 0.f);
        float area = 0.f;
        if (real) {
            int bidx = (int)~(unsigned)key;
            bx = boxes[(size_t)b * N_ + bidx];
            area = (bx.z - bx.x) * (bx.w - bx.y);
        }
        bool alive = real;
        for (int r = 0; r < nacc && alive; r++)
            if (iou_gt(acc_box[r], acc_area[r], bx, area)) alive = false;

        // ---- compact survivors (order-preserving) ----
        unsigned ball = __ballot_sync(FULLM, alive);
        if (ln == 0) s_wcnt[w] = __popc(ball);
        __syncthreads();
        if (w == 0) {
            int x = s_wcnt[ln];
            int ix = x;
            #pragma unroll
            for (int o = 1; o < 32; o <<= 1) {
                int t = __shfl_up_sync(FULLM, ix, o);
                if (ln >= o) ix += t;
            }
            s_wcnt[ln] = ix - x;
            if (ln == 31) s_S = ix;
        }
        __syncthreads();
        const int S = s_S;
        if (alive) {
            int pos = s_wcnt[w] + __popc(ball & ((1u << ln) - 1u));
            s_key[pos]  = key;
            s_box[pos]  = bx;
            s_area[pos] = area;
        }
        __syncthreads();

        // ---- greedy over survivors, 32 per chunk (one warp per candidate) ----
        const int nacc0 = nacc;
        for (int c0 = 0; c0 < S && nacc < MAXD; c0 += 32) {
            int q = c0 + w;
            bool has = q < S;
            float4 cb = make_float4(0.f, 0.f, 0.f, 0.f);
            float ca = 0.f;
            if (has) { cb = s_box[q]; ca = s_area[q]; }

            // external vs boxes accepted during THIS window only
            bool supp = !has;
            for (int r0 = nacc0; r0 < nacc && !supp; r0 += 32) {
                int ai = r0 + ln;
                bool sbit = false;
                if (ai < nacc) sbit = iou_gt(acc_box[ai], acc_area[ai], cb, ca);
                if (__ballot_sync(FULLM, sbit)) supp = true;
            }
            // intra-chunk: earlier candidate c0+ln vs candidate q
            bool s2 = false;
            if (ln < w && (c0 + ln) < S)
                s2 = iou_gt(s_box[c0 + ln], s_area[c0 + ln], cb, ca);
            unsigned m = __ballot_sync(FULLM, s2);
            if (ln == 0) { s_ext[w] = (unsigned char)(!supp && has); s_intra[w] = m; }
            __syncthreads();

            // warp 0: resolve + write accepted (parallel across lanes)
            if (w == 0) {
                bool ok = (s_ext[ln] != 0);
                unsigned mask = s_intra[ln];
                unsigned eligible = __ballot_sync(FULLM, ok);
                unsigned confl = __ballot_sync(FULLM, ok && ((mask & eligible) != 0u));
                unsigned acceptb;
                if (confl == 0u) {
                    acceptb = eligible;
                } else {
                    unsigned accb = 0;
                    #pragma unroll 1
                    for (int t = 0; t < 32; t++) {
                        bool bit = ok && (ln == t) && ((mask & accb) == 0u);
                        accb |= __ballot_sync(FULLM, bit);
                    }
                    acceptb = accb;
                }
                int navail = MAXD - nacc;
                if (__popc(acceptb) > navail) {
                    bool keep = ((acceptb >> ln) & 1u) &&
                                (__popc(acceptb & ((1u << ln) - 1u)) < navail);
                    acceptb = __ballot_sync(FULLM, keep);
                }
                if ((acceptb >> ln) & 1u) {
                    int pos = nacc + __popc(acceptb & ((1u << ln) - 1u));
                    float4 ab = s_box[c0 + ln];
                    acc_box[pos]  = ab;
                    acc_area[pos] = s_area[c0 + ln];
                    unsigned long long kk = s_key[c0 + ln];
                    g_sel_idx[L][pos]   = (int)~(unsigned)kk;
                    g_sel_score[L][pos] = __uint_as_float((unsigned)(kk >> 32) ^ 0x80000000u);
                }
                if (ln == 0) s_accept = acceptb;
            }
            __syncthreads();
            nacc += __popc(s_accept);
        }
        cur = e;
    }
    if (tid == 0) g_nacc[L] = nacc;
}

// ============================ top-300 via radix-select + sort ============================
__global__ __launch_bounds__(1024) void topk_kernel(const float4* __restrict__ boxes,
                                                    float* __restrict__ out) {
    __shared__ int hist[1024];
    __shared__ int wsum[32];
    __shared__ int s_bt, s_pos;
    __shared__ unsigned long long sk[1024];

    const int b = blockIdx.x, tid = threadIdx.x;
    const int lane = tid & 31, w = tid >> 5;
    const int TOT = C_ * MAXD; // 6000

    hist[tid] = 0;
    sk[tid] = 0ULL;
    if (tid == 0) s_pos = 0;
    __syncthreads();

    for (int t = tid; t < TOT; t += 1024) {
        int c = t / MAXD, m = t % MAXD;
        int Ln = b * C_ + c;
        if (m < g_nacc[Ln]) {
            float s = g_sel_score[Ln][m];
            int bk = (int)(s * 1024.f);
            if (bk > 1023) bk = 1023;
            atomicAdd(&hist[bk], 1);
        }
    }
    __syncthreads();

    int v = hist[1023 - tid];
    int incl = v;
    #pragma unroll
    for (int o = 1; o < 32; o <<= 1) {
        int t = __shfl_up_sync(FULLM, incl, o);
        if (lane >= o) incl += t;
    }
    if (lane == 31) wsum[w] = incl;
    __syncthreads();
    if (w == 0) {
        int x = wsum[lane];
        #pragma unroll
        for (int o = 1; o < 32; o <<= 1) {
            int t = __shfl_up_sync(FULLM, x, o);
            if (lane >= o) x += t;
        }
        wsum[lane] = x;
    }
    __syncthreads();
    int suffix = ((w > 0) ? wsum[w - 1] : 0) + incl;
    int suffix_prev = suffix - v;
    if (suffix >= MAXD && suffix_prev < MAXD) s_bt = 1023 - tid;
    if (tid == 1023 && suffix < MAXD) s_bt = 0;
    __syncthreads();
    const int bt = s_bt;

    for (int t = tid; t < TOT; t += 1024) {
        int c = t / MAXD, m = t % MAXD;
        int Ln = b * C_ + c;
        if (m < g_nacc[Ln]) {
            float s = g_sel_score[Ln][m];
            int bk = (int)(s * 1024.f);
            if (bk > 1023) bk = 1023;
            if (bk >= bt) {
                unsigned sb = __float_as_uint(s) | 0x80000000u;
                unsigned long long key = ((unsigned long long)sb << 32) | (unsigned)(~(unsigned)t);
                int pos = atomicAdd(&s_pos, 1);
                if (pos < 1024) sk[pos] = key;
            }
        }
    }
    __syncthreads();

    unsigned long long key = sk[tid];
    __syncthreads();
    key = block_sort_desc_1024(key, sk, tid);

    if (tid < MAXD) {
        float bx = -1.f, by = -1.f, bz = -1.f, bw = -1.f, scv = -1.f, lb = -1.f;
        if (key != 0ULL) {
            unsigned f = ~(unsigned)key;
            int c = f / MAXD, m = f % MAXD;
            int Ln = b * C_ + c;
            int idx = g_sel_idx[Ln][m];
            float4 bb = boxes[(size_t)b * N_ + idx];
            bx = bb.x; by = bb.y; bz = bb.z; bw = bb.w;
            scv = g_sel_score[Ln][m];
            lb = (float)c;
        }
        int o = b * MAXD + tid;
        out[o * 4 + 0] = bx; out[o * 4 + 1] = by;
        out[o * 4 + 2] = bz; out[o * 4 + 3] = bw;
        out[B_ * MAXD * 4 + o] = scv;
        out[B_ * MAXD * 4 + B_ * MAXD + o] = lb;
    }
}

// ============================ launch ============================
extern "C" void kernel_launch(void* const* d_in, const int* in_sizes, int n_in,
                              void* d_out, int out_size) {
    const float* boxes = (const float*)d_in[0]; // (B, N, 4) f32
    const float* cls   = (const float*)d_in[1]; // (B, N, C) f32
    float*       out   = (float*)d_out;         // [boxes | scores | labels] f32

    nms_fused  <<<LANES, 1024>>>(cls, (const float4*)boxes);
    topk_kernel<<<B_, 1024>>>((const float4*)boxes, out);
}